// round 4
// baseline (speedup 1.0000x reference)
#include <cuda_runtime.h>
#include <cuda_bf16.h>

// Shapes fixed by reference setup_inputs
#define FF 2
#define BB 64
#define SS 512
#define DD 768
#define NPAIR (FF * BB)        // 128
#define NSLICE 4               // CTAs per pair (equal slices of compacted list)
#define GRID (NPAIR * NSLICE)  // 512 -> single wave at 5 CTAs/SM

__device__ float        g_partial[GRID];
__device__ unsigned int g_count = 0;

__global__ __launch_bounds__(256, 5) void nl_fused_kernel(
    const float* __restrict__ tok,
    const float* __restrict__ sent,
    const int* __restrict__ mask,
    float* __restrict__ out)
{
    const int fb   = blockIdx.x >> 2;   // pair
    const int q    = blockIdx.x & 3;    // slice of this pair's nonzero rows
    const int tid  = threadIdx.x;
    const int warp = tid >> 5;
    const int lane = tid & 31;

    __shared__ float s_sent[DD];
    __shared__ short s_idx[SS];         // compacted nonzero row indices (full pair)
    __shared__ int   s_cnt[16];         // per-32-row-segment counts
    __shared__ float s_acc[8];

    for (int i = tid; i < DD; i += 256)
        s_sent[i] = sent[(size_t)fb * DD + i];

    // ---- Deterministic compaction of ALL 512 rows of this pair ----
    // 8 warps x 2 segments of 32 rows, in row order -> ordered compact list.
    const int* __restrict__ mrow = mask + (size_t)fb * SS;
    int m0, m1; unsigned bal0, bal1;
    {
        const int seg0 = warp * 2, seg1 = warp * 2 + 1;
        m0 = mrow[seg0 * 32 + lane];
        m1 = mrow[seg1 * 32 + lane];
        bal0 = __ballot_sync(0xFFFFFFFFu, m0 != 0);
        bal1 = __ballot_sync(0xFFFFFFFFu, m1 != 0);
        if (lane == 0) { s_cnt[seg0] = __popc(bal0); s_cnt[seg1] = __popc(bal1); }
    }
    __syncthreads();

    int pre[17];                        // exclusive prefix over 16 segments
    pre[0] = 0;
    #pragma unroll
    for (int i = 0; i < 16; i++) pre[i + 1] = pre[i] + s_cnt[i];
    const int n_pair = pre[16];
    {
        const int seg0 = warp * 2, seg1 = warp * 2 + 1;
        if (m0 != 0)
            s_idx[pre[seg0] + __popc(bal0 & ((1u << lane) - 1u))] = (short)(seg0 * 32 + lane);
        if (m1 != 0)
            s_idx[pre[seg1] + __popc(bal1 & ((1u << lane) - 1u))] = (short)(seg1 * 32 + lane);
    }
    __syncthreads();

    // ---- This CTA's equal slice of the pair's nonzero rows ----
    const int i_begin = (q * n_pair) >> 2;
    const int i_end   = ((q + 1) * n_pair) >> 2;

    const float4* __restrict__ tok4  = (const float4*)(tok + (size_t)fb * SS * DD);
    const float4* __restrict__ sent4 = (const float4*)s_sent;

    float acc = 0.0f;
    for (int i = i_begin + warp; i < i_end; i += 8) {
        const int s = s_idx[i];
        const float4* __restrict__ row = tok4 + (size_t)s * (DD / 4);
        float4 a0 = row[lane +   0];
        float4 a1 = row[lane +  32];
        float4 a2 = row[lane +  64];
        float4 a3 = row[lane +  96];
        float4 a4 = row[lane + 128];
        float4 a5 = row[lane + 160];
        float4 b0 = sent4[lane +   0];
        float4 b1 = sent4[lane +  32];
        float4 b2 = sent4[lane +  64];
        float4 b3 = sent4[lane +  96];
        float4 b4 = sent4[lane + 128];
        float4 b5 = sent4[lane + 160];
        acc += a0.x*b0.x + a0.y*b0.y + a0.z*b0.z + a0.w*b0.w
             + a1.x*b1.x + a1.y*b1.y + a1.z*b1.z + a1.w*b1.w
             + a2.x*b2.x + a2.y*b2.y + a2.z*b2.z + a2.w*b2.w
             + a3.x*b3.x + a3.y*b3.y + a3.z*b3.z + a3.w*b3.w
             + a4.x*b4.x + a4.y*b4.y + a4.z*b4.z + a4.w*b4.w
             + a5.x*b5.x + a5.y*b5.y + a5.z*b5.z + a5.w*b5.w;
    }

    // ---- Block reduction (fixed order -> deterministic) ----
    #pragma unroll
    for (int o = 16; o; o >>= 1)
        acc += __shfl_xor_sync(0xFFFFFFFFu, acc, o);
    if (lane == 0) s_acc[warp] = acc;
    __syncthreads();

    if (tid == 0) {
        float t = 0.0f;
        #pragma unroll
        for (int w = 0; w < 8; w++) t += s_acc[w];
        g_partial[blockIdx.x] = t;
        __threadfence();
        unsigned int done = atomicAdd(&g_count, 1u);
        s_acc[0] = (done == GRID - 1) ? 1.0f : 0.0f;
    }
    __syncthreads();

    if (s_acc[0] != 0.0f) {
        // Last CTA finalizes: 128 lanes each own one (f,b) pair.
        __threadfence();
        __shared__ float s_val[NPAIR];
        if (tid < NPAIR) {
            float t = 0.0f;
            #pragma unroll
            for (int c = 0; c < NSLICE; c++)
                t += g_partial[tid * NSLICE + c];
            s_val[tid] = t / (t + 1e-9f);
        }
        __syncthreads();
        if (tid == 0) {
            float r = 0.0f;
            #pragma unroll
            for (int i = 0; i < NPAIR; i++) r += s_val[i];
            *out = r / (float)FF;
            g_count = 0;  // reset for next graph replay
        }
    }
}

extern "C" void kernel_launch(void* const* d_in, const int* in_sizes, int n_in,
                              void* d_out, int out_size) {
    const float* tok  = (const float*)d_in[0];
    const float* sent = (const float*)d_in[1];
    const int*   mask = (const int*)d_in[2];
    float* out = (float*)d_out;

    nl_fused_kernel<<<GRID, 256>>>(tok, sent, mask, out);
}

// round 5
// speedup vs baseline: 1.3463x; 1.3463x over previous
#include <cuda_runtime.h>
#include <cuda_bf16.h>

// Shapes fixed by reference setup_inputs
#define FF 2
#define BB 64
#define SS 512
#define DD 768
#define NPAIR (FF * BB)        // 128
#define NSLICE 4               // CTAs per pair, equal slices of compacted rows
#define GRID (NPAIR * NSLICE)  // 512

__device__ float        g_partial[GRID];
__device__ unsigned int g_count = 0;

__global__ __launch_bounds__(256) void nl_fused_kernel(
    const float* __restrict__ tok,
    const float* __restrict__ sent,
    const int* __restrict__ mask,
    float* __restrict__ out)
{
    const int fb   = blockIdx.x >> 2;   // pair
    const int q    = blockIdx.x & 3;    // slice
    const int tid  = threadIdx.x;
    const int warp = tid >> 5;
    const int lane = tid & 31;

    __shared__ float s_sent[DD];
    __shared__ short s_idx[SS];         // compacted nonzero row indices (whole pair)
    __shared__ int   s_cnt[16];
    __shared__ float s_acc[8];

    for (int i = tid; i < DD; i += 256)
        s_sent[i] = sent[(size_t)fb * DD + i];

    // ---- Compact all 512 rows of this pair (ordered, deterministic) ----
    const int* __restrict__ mrow = mask + (size_t)fb * SS;
    const int seg0 = warp * 2, seg1 = warp * 2 + 1;
    const int m0 = mrow[seg0 * 32 + lane];
    const int m1 = mrow[seg1 * 32 + lane];
    const unsigned bal0 = __ballot_sync(0xFFFFFFFFu, m0 != 0);
    const unsigned bal1 = __ballot_sync(0xFFFFFFFFu, m1 != 0);
    if (lane == 0) { s_cnt[seg0] = __popc(bal0); s_cnt[seg1] = __popc(bal1); }
    __syncthreads();

    int pre[17];
    pre[0] = 0;
    #pragma unroll
    for (int i = 0; i < 16; i++) pre[i + 1] = pre[i] + s_cnt[i];
    const int n_pair = pre[16];
    if (m0 != 0)
        s_idx[pre[seg0] + __popc(bal0 & ((1u << lane) - 1u))] = (short)(seg0 * 32 + lane);
    if (m1 != 0)
        s_idx[pre[seg1] + __popc(bal1 & ((1u << lane) - 1u))] = (short)(seg1 * 32 + lane);
    __syncthreads();

    // ---- Sentence slice in REGISTERS (hot loop touches no smem for b) ----
    const float4* __restrict__ sent4 = (const float4*)s_sent;
    const float4 b0 = sent4[lane +   0];
    const float4 b1 = sent4[lane +  32];
    const float4 b2 = sent4[lane +  64];
    const float4 b3 = sent4[lane +  96];
    const float4 b4 = sent4[lane + 128];
    const float4 b5 = sent4[lane + 160];

    // ---- Equal slice of the pair's nonzero rows ----
    const int i_begin = (q * n_pair) >> 2;
    const int i_end   = ((q + 1) * n_pair) >> 2;

    const float4* __restrict__ tok4 = (const float4*)(tok + (size_t)fb * SS * DD);

    float acc = 0.0f;
    for (int i = i_begin + warp; i < i_end; i += 8) {
        const int s = s_idx[i];
        const float4* __restrict__ row = tok4 + (size_t)s * (DD / 4);
        float4 a0 = row[lane +   0];
        float4 a1 = row[lane +  32];
        float4 a2 = row[lane +  64];
        float4 a3 = row[lane +  96];
        float4 a4 = row[lane + 128];
        float4 a5 = row[lane + 160];
        acc += a0.x*b0.x + a0.y*b0.y + a0.z*b0.z + a0.w*b0.w
             + a1.x*b1.x + a1.y*b1.y + a1.z*b1.z + a1.w*b1.w
             + a2.x*b2.x + a2.y*b2.y + a2.z*b2.z + a2.w*b2.w
             + a3.x*b3.x + a3.y*b3.y + a3.z*b3.z + a3.w*b3.w
             + a4.x*b4.x + a4.y*b4.y + a4.z*b4.z + a4.w*b4.w
             + a5.x*b5.x + a5.y*b5.y + a5.z*b5.z + a5.w*b5.w;
    }

    // ---- Block reduction ----
    #pragma unroll
    for (int o = 16; o; o >>= 1)
        acc += __shfl_xor_sync(0xFFFFFFFFu, acc, o);
    if (lane == 0) s_acc[warp] = acc;
    __syncthreads();

    if (tid == 0) {
        float t = 0.0f;
        #pragma unroll
        for (int w = 0; w < 8; w++) t += s_acc[w];
        g_partial[blockIdx.x] = t;
        __threadfence();
        unsigned int done = atomicAdd(&g_count, 1u);
        s_acc[0] = (done == GRID - 1) ? 1.0f : 0.0f;
    }
    __syncthreads();

    if (s_acc[0] != 0.0f) {
        // Last CTA finalizes: 128 lanes each own one (f,b) pair.
        __threadfence();
        __shared__ float s_val[NPAIR];
        if (tid < NPAIR) {
            float t = 0.0f;
            #pragma unroll
            for (int c = 0; c < NSLICE; c++)
                t += g_partial[tid * NSLICE + c];
            s_val[tid] = t / (t + 1e-9f);
        }
        __syncthreads();
        if (tid == 0) {
            float r = 0.0f;
            #pragma unroll
            for (int i = 0; i < NPAIR; i++) r += s_val[i];
            *out = r / (float)FF;
            g_count = 0;  // reset for next graph replay
        }
    }
}

extern "C" void kernel_launch(void* const* d_in, const int* in_sizes, int n_in,
                              void* d_out, int out_size) {
    const float* tok  = (const float*)d_in[0];
    const float* sent = (const float*)d_in[1];
    const int*   mask = (const int*)d_in[2];
    float* out = (float*)d_out;

    nl_fused_kernel<<<GRID, 256>>>(tok, sent, mask, out);
}